// round 4
// baseline (speedup 1.0000x reference)
#include <cuda_runtime.h>
#include <cstdint>

// LSTM: B=32, T=1024, I=512, H=512, gates G=4H=2048
// out layout: outs[B][T][H] (16777216 floats) | h_T[B][H] | c_T[B][H]

#define NB 32
#define NT 1024
#define NI 512
#define NH 512
#define NG 2048

#define GROUPS 4
#define GBLK 32            // blocks per group
#define GBATCH 8           // batches per group
#define SCAN_BLOCKS (GROUPS * GBLK)
#define SCAN_THREADS 512
#define WPAD 516           // padded row stride (floats); 516*4B = 2064B (16B-aligned, bank-shifted)

// ---------------- device scratch ----------------
__device__ float g_xg[(size_t)NT * NB * NG];            // [t][b][g]
__device__ float g_h[2][GROUPS][GBATCH][NH];            // double-buffered per-group hidden
__device__ unsigned g_bars[GROUPS * 32];                // one padded counter per group

// ---------------- f32x2 helpers ----------------
__device__ __forceinline__ unsigned long long pk2(float lo, float hi) {
    unsigned long long r;
    asm("mov.b64 %0, {%1, %2};" : "=l"(r) : "f"(lo), "f"(hi));
    return r;
}
__device__ __forceinline__ void fma2(unsigned long long& acc,
                                     unsigned long long a, unsigned long long b) {
    asm("fma.rn.f32x2 %0, %1, %2, %0;" : "+l"(acc) : "l"(a), "l"(b));
}
__device__ __forceinline__ float2 upk(unsigned long long v) {
    float2 f;
    asm("mov.b64 {%0, %1}, %2;" : "=f"(f.x), "=f"(f.y) : "l"(v));
    return f;
}
__device__ __forceinline__ float sigf(float x) {
    return 1.0f / (1.0f + __expf(-x));
}
__device__ __forceinline__ float tanhfast(float x) {
    return 1.0f - 2.0f / (__expf(2.0f * x) + 1.0f);
}

// ---------------- init (every replay) ----------------
__global__ void k_init() {
    int t = threadIdx.x + blockIdx.x * blockDim.x;
    int n = gridDim.x * blockDim.x;
    for (int i = t; i < GROUPS * 32; i += n) g_bars[i] = 0u;
    float* h = &g_h[0][0][0][0];
    for (int i = t; i < 2 * GROUPS * GBATCH * NH; i += n) h[i] = 0.0f;
}

// ---------------- GEMM: xg[t][b][g] = x . W_ih^T + b_ih + b_hh (unchanged) ----------------
__global__ void __launch_bounds__(256) k_gemm(const float* __restrict__ X,
                                              const float* __restrict__ Wih,
                                              const float* __restrict__ bih,
                                              const float* __restrict__ bhh) {
    __shared__ float As[2][16][132];
    __shared__ float Bs[2][16][132];

    const int tid = threadIdx.x;
    const int m0 = blockIdx.y * 128;
    const int n0 = blockIdx.x * 128;
    const int tx = tid & 15;
    const int ty = tid >> 4;
    const int lr = tid >> 2;
    const int lq = tid & 3;

    unsigned long long acc[8][4];
#pragma unroll
    for (int i = 0; i < 8; i++)
#pragma unroll
        for (int j = 0; j < 4; j++) acc[i][j] = 0ull;

    float4 aR[2], bR[2];
#pragma unroll
    for (int l = 0; l < 2; l++) {
        aR[l] = __ldg((const float4*)(X   + (size_t)(m0 + lr + 64 * l) * NI + 4 * lq));
        bR[l] = __ldg((const float4*)(Wih + (size_t)(n0 + lr + 64 * l) * NI + 4 * lq));
    }

    int buf = 0;
    for (int it = 0; it < 32; it++) {
#pragma unroll
        for (int l = 0; l < 2; l++) {
            const float* av = (const float*)&aR[l];
            const float* bv = (const float*)&bR[l];
#pragma unroll
            for (int i = 0; i < 4; i++) {
                As[buf][4 * lq + i][lr + 64 * l] = av[i];
                Bs[buf][4 * lq + i][lr + 64 * l] = bv[i];
            }
        }
        __syncthreads();

        if (it < 31) {
            const int k0 = (it + 1) * 16;
#pragma unroll
            for (int l = 0; l < 2; l++) {
                aR[l] = __ldg((const float4*)(X   + (size_t)(m0 + lr + 64 * l) * NI + k0 + 4 * lq));
                bR[l] = __ldg((const float4*)(Wih + (size_t)(n0 + lr + 64 * l) * NI + k0 + 4 * lq));
            }
        }

#pragma unroll
        for (int k = 0; k < 16; k++) {
            float4 a0 = *(const float4*)&As[buf][k][ty * 8];
            float4 a1 = *(const float4*)&As[buf][k][ty * 8 + 4];
            float4 b0 = *(const float4*)&Bs[buf][k][tx * 8];
            float4 b1 = *(const float4*)&Bs[buf][k][tx * 8 + 4];
            unsigned long long bb[4] = {pk2(b0.x, b0.y), pk2(b0.z, b0.w),
                                        pk2(b1.x, b1.y), pk2(b1.z, b1.w)};
            float av[8] = {a0.x, a0.y, a0.z, a0.w, a1.x, a1.y, a1.z, a1.w};
#pragma unroll
            for (int i = 0; i < 8; i++) {
                unsigned long long aa = pk2(av[i], av[i]);
#pragma unroll
                for (int j = 0; j < 4; j++) fma2(acc[i][j], aa, bb[j]);
            }
        }
        buf ^= 1;
        __syncthreads();
    }

    const int nb = n0 + tx * 8;
    float bias[8];
#pragma unroll
    for (int j = 0; j < 8; j++) bias[j] = __ldg(bih + nb + j) + __ldg(bhh + nb + j);

#pragma unroll
    for (int i = 0; i < 8; i++) {
        const int m = m0 + ty * 8 + i;
        const int t = m & (NT - 1);
        const int b = m >> 10;
        float* orow = g_xg + ((size_t)t * NB + b) * NG + nb;
#pragma unroll
        for (int j2 = 0; j2 < 4; j2++) {
            float2 v = upk(acc[i][j2]);
            v.x += bias[2 * j2];
            v.y += bias[2 * j2 + 1];
            *(float2*)(orow + 2 * j2) = v;
        }
    }
}

// ---------------- persistent scan kernel (v3: batch-grouped) ----------------
// 4 independent groups of 32 blocks; group gid owns batches [8*gid, 8*gid+8).
// Block r in group owns hidden units j0 = r*16..+15 (64 gate rows, W in smem).
// Per step: stage group's h (16KB) -> 16 warps: warp (c = w>>2, q = w&3)
// computes gate q's 16 rows x 8 batches over K-chunk c (128 k, k-packed f32x2),
// lane (rp, bp) register tile u in {rp, rp+8}, b in {bp, bp+4} -> sRed[4][512]
// -> 128-thread finalize (c-state in regs) -> publish h -> 32-block barrier.
__global__ void __launch_bounds__(SCAN_THREADS, 1) k_scan(float* __restrict__ out,
                                                          const float* __restrict__ Whh) {
    extern __shared__ float sm[];
    float* sW   = sm;                     // [64][WPAD]  gate-row slices
    float* sH   = sW + 64 * WPAD;         // [8][WPAD]   group hidden state
    float* sRed = sH + 8 * WPAD;          // [4][512]    K-chunk partials

    const int tid = threadIdx.x;
    const int bid = blockIdx.x;
    const int gid = bid >> 5;             // group
    const int r   = bid & 31;             // rank in group
    const int j0  = r * 16;

    // Load this block's 64 W_hh rows: sW row gl = q*16 + u  <- W_hh[q*512 + j0 + u][:]
    for (int idx = tid; idx < 64 * 512; idx += SCAN_THREADS) {
        const int gl = idx >> 9;
        const int k  = idx & 511;
        const int q  = gl >> 4;
        const int u  = gl & 15;
        sW[gl * WPAD + k] = __ldcg(Whh + (size_t)(q * 512 + j0 + u) * NH + k);
    }

    // dot-phase roles
    const int w    = tid >> 5;
    const int q    = w & 3;               // gate
    const int c    = w >> 2;              // K-chunk: k in [128c, 128c+128)
    const int lane = tid & 31;
    const int rp   = lane >> 2;           // unit: u in {rp, rp+8}
    const int bp   = lane & 3;            // batch: b in {bp, bp+4}

    // finalize roles (tid < 128): tid = fb*16 + u
    const int fu = tid & 15;
    const int fb = tid >> 4;

    unsigned mybar_tgt = 0;
    float creg = 0.0f;
    float xg[4];

    __syncthreads();   // sW ready

    // prefetch xg for t=0
    if (tid < 128) {
        const float* xrow = g_xg + ((size_t)0 * NB + gid * GBATCH + fb) * NG + j0 + fu;
#pragma unroll
        for (int qq = 0; qq < 4; qq++) xg[qq] = __ldcg(xrow + qq * 512);
    }

    for (int t = 0; t < NT; t++) {
        const int cur = t & 1;
        const int nxt = cur ^ 1;

        // ---- stage group's h (16KB) from L2 into smem ----
        {
            const float4* hp = (const float4*)&g_h[cur][gid][0][0];   // 1024 float4
#pragma unroll
            for (int i = 0; i < 2; i++) {
                const int f = tid + i * SCAN_THREADS;
                float4 v = __ldcg(hp + f);
                const int b  = f >> 7;
                const int k4 = (f & 127) * 4;
                *(float4*)&sH[b * WPAD + k4] = v;
            }
        }
        __syncthreads();

        // ---- dot phase (k-packed f32x2) ----
        unsigned long long acc00 = 0, acc01 = 0, acc10 = 0, acc11 = 0;
        {
            const ulonglong2* H0 = (const ulonglong2*)(sH + (size_t)bp * WPAD + 128 * c);
            const ulonglong2* H1 = (const ulonglong2*)(sH + (size_t)(bp + 4) * WPAD + 128 * c);
            const ulonglong2* W0 = (const ulonglong2*)(sW + (size_t)(q * 16 + rp) * WPAD + 128 * c);
            const ulonglong2* W1 = (const ulonglong2*)(sW + (size_t)(q * 16 + rp + 8) * WPAD + 128 * c);
#pragma unroll
            for (int kk = 0; kk < 32; kk++) {   // 4 k per iter
                const ulonglong2 h0 = H0[kk];
                const ulonglong2 h1 = H1[kk];
                const ulonglong2 w0 = W0[kk];
                const ulonglong2 w1 = W1[kk];
                fma2(acc00, h0.x, w0.x); fma2(acc00, h0.y, w0.y);
                fma2(acc01, h1.x, w0.x); fma2(acc01, h1.y, w0.y);
                fma2(acc10, h0.x, w1.x); fma2(acc10, h0.y, w1.y);
                fma2(acc11, h1.x, w1.x); fma2(acc11, h1.y, w1.y);
            }
        }
        // partial store: col = q*128 + b*16 + u
        {
            float2 p;
            p = upk(acc00); sRed[c * 512 + q * 128 + bp * 16 + rp]            = p.x + p.y;
            p = upk(acc10); sRed[c * 512 + q * 128 + bp * 16 + rp + 8]        = p.x + p.y;
            p = upk(acc01); sRed[c * 512 + q * 128 + (bp + 4) * 16 + rp]      = p.x + p.y;
            p = upk(acc11); sRed[c * 512 + q * 128 + (bp + 4) * 16 + rp + 8]  = p.x + p.y;
        }
        __syncthreads();

        // ---- finalize: sum 4 chunk partials, cell update, publish ----
        if (tid < 128) {
            float gate[4];
#pragma unroll
            for (int qq = 0; qq < 4; qq++) {
                gate[qq] = xg[qq]
                         + sRed[          qq * 128 + tid]
                         + sRed[1 * 512 + qq * 128 + tid]
                         + sRed[2 * 512 + qq * 128 + tid]
                         + sRed[3 * 512 + qq * 128 + tid];
            }
            const float ig = sigf(gate[0]);
            const float fg = sigf(gate[1]);
            const float gv = tanhfast(gate[2]);
            const float og = sigf(gate[3]);
            creg = fg * creg + ig * gv;
            const float hn = og * tanhfast(creg);

            const int j  = j0 + fu;
            const int bg = gid * GBATCH + fb;
            out[((size_t)bg * NT + t) * NH + j] = hn;
            __stcg(&g_h[nxt][gid][fb][j], hn);
            if (t == NT - 1) {
                out[(size_t)NB * NT * NH + (size_t)bg * NH + j] = hn;                       // h_T
                out[(size_t)NB * NT * NH + (size_t)NB * NH + (size_t)bg * NH + j] = creg;   // c_T
            }
            // prefetch next step's xg while others drain
            if (t + 1 < NT) {
                const float* xrow = g_xg + ((size_t)(t + 1) * NB + bg) * NG + j0 + fu;
#pragma unroll
                for (int qq = 0; qq < 4; qq++) xg[qq] = __ldcg(xrow + qq * 512);
            }
        }
        __syncthreads();

        // ---- group barrier (32 blocks, monotonic counter) ----
        if (tid == 0) {
            __threadfence();
            atomicAdd(&g_bars[gid * 32], 1u);
            mybar_tgt += GBLK;
            volatile unsigned* bp2 = &g_bars[gid * 32];
            while (*bp2 < mybar_tgt) { __nanosleep(20); }
            __threadfence();
        }
        __syncthreads();
    }
}

// ---------------- launch ----------------
extern "C" void kernel_launch(void* const* d_in, const int* in_sizes, int n_in,
                              void* d_out, int out_size) {
    const float* x    = (const float*)d_in[0];
    const float* Wih  = (const float*)d_in[1];
    const float* Whh  = (const float*)d_in[2];
    const float* bih  = (const float*)d_in[3];
    const float* bhh  = (const float*)d_in[4];
    float* out = (float*)d_out;

    const int scan_smem = (64 * WPAD + 8 * WPAD + 4 * 512) * (int)sizeof(float);  // 156,800 B
    cudaFuncSetAttribute(k_scan, cudaFuncAttributeMaxDynamicSharedMemorySize, scan_smem);

    k_init<<<16, 256>>>();

    dim3 ggrid(NG / 128, (NB * NT) / 128);   // (16, 256)
    k_gemm<<<ggrid, 256>>>(x, Wih, bih, bhh);

    k_scan<<<SCAN_BLOCKS, SCAN_THREADS, scan_smem>>>(out, Whh);
}